// round 5
// baseline (speedup 1.0000x reference)
#include <cuda_runtime.h>
#include <cstdint>

// ---------------------------------------------------------------------------
// MultiHeadAttention (B=4, S=2048, D=1024, H=16, DK=64).
// Round 5: software-pipelined (register-prefetch) dense GEMMs and attention.
// tf32 mma.sync everywhere; polynomial exp on FMA pipe.
// Output layout: d_out = [ x (8,388,608 f32) | attn (268,435,456 f32) ]
// ---------------------------------------------------------------------------

namespace {
constexpr int B  = 4;
constexpr int S  = 2048;
constexpr int D  = 1024;
constexpr int H  = 16;
constexpr int DK = 64;
constexpr size_t QH_ELEMS   = (size_t)B * H * S * DK;        // 8,388,608
constexpr size_t X_ELEMS    = (size_t)B * S * D;             // 8,388,608
constexpr size_t ATTN_ELEMS = (size_t)B * H * S * (size_t)S; // 268,435,456

// dense-GEMM tiling: CTA 128x128, warp 64x32 (2x4 warps), K-chunk 32,
// single smem stage + register prefetch of next chunk.
constexpr int KC = 32;
constexpr int GST = 36;                               // ≡4 mod 32 -> conflict-free
constexpr int GEMM_SMEM = 2 * 128 * GST * 4;          // 36,864 B (< 48K default)

// attention smem layout (uint32 words)
constexpr int AQ_OFF = 0;                  // Qs[128][68]
constexpr int AK_OFF = AQ_OFF + 128 * 68;  // Ks[64][68]
constexpr int AV_OFF = AK_OFF + 64 * 68;   // Vt[64][68]  (d rows, key cols)
constexpr int AP_OFF = AV_OFF + 64 * 68;   // Ps[128][68]
constexpr int ARS_OFF = AP_OFF + 128 * 68; // rs[2][128] floats
constexpr int AIV_OFF = ARS_OFF + 256;     // sinv[128] floats
constexpr int ATTN_SMEM = (AIV_OFF + 128) * 4;   // 105,984 B
}

// Scratch (allocation-free rule: __device__ globals)
__device__ float g_qh[QH_ELEMS];
__device__ float g_kh[QH_ELEMS];
__device__ float g_vt[QH_ELEMS];           // V transposed: [bh][d][s]
__device__ float g_ctx[X_ELEMS];
__device__ float g_x[X_ELEMS];
__device__ float g_rinv[(size_t)B * H * S];
__device__ float g_wqt[(size_t)D * D];     // Wq^T  [N][K]
__device__ float g_wfct[(size_t)D * D];    // Wfc^T [N][K]

// ---------------------------------------------------------------------------
// helpers
// ---------------------------------------------------------------------------
__device__ __forceinline__ uint32_t f2tf32(float x) {
    uint32_t r;
    asm("cvt.rna.tf32.f32 %0, %1;" : "=r"(r) : "f"(x));
    return r;
}
__device__ __forceinline__ void mma_tf32(float* d, const uint32_t* a, const uint32_t* b) {
    asm volatile(
        "mma.sync.aligned.m16n8k8.row.col.f32.tf32.tf32.f32 "
        "{%0,%1,%2,%3}, {%4,%5,%6,%7}, {%8,%9}, {%0,%1,%2,%3};"
        : "+f"(d[0]), "+f"(d[1]), "+f"(d[2]), "+f"(d[3])
        : "r"(a[0]), "r"(a[1]), "r"(a[2]), "r"(a[3]), "r"(b[0]), "r"(b[1]));
}
// exp via FMA pipe: magic-number range reduction + deg-5 poly (rel err ~2e-6).
__device__ __forceinline__ float fast_exp(float x) {
    const float L2E = 1.4426950408889634f;
    float t = fmaf(x, L2E, 12582912.0f);
    float n = t - 12582912.0f;
    float f = fmaf(x, L2E, -n);
    float p = 0.0013333558f;
    p = fmaf(p, f, 0.0096181291f);
    p = fmaf(p, f, 0.0555041087f);
    p = fmaf(p, f, 0.2402265069f);
    p = fmaf(p, f, 0.6931471806f);
    p = fmaf(p, f, 1.0f);
    return __int_as_float(__float_as_int(p) + (__float_as_int(t) << 23));
}

// ---------------------------------------------------------------------------
// K0: transpose Wq and Wfc once -> g_wqt / g_wfct  (W is [K=1024][N=1024])
// ---------------------------------------------------------------------------
__global__ __launch_bounds__(256) void transpose_kernel(
    const float* __restrict__ Wq, const float* __restrict__ Wfc)
{
    __shared__ float tile[32][33];
    const float* src = blockIdx.z ? Wfc : Wq;
    float*       dst = blockIdx.z ? g_wfct : g_wqt;
    int x = blockIdx.x * 32 + threadIdx.x;
    int y = blockIdx.y * 32 + threadIdx.y;
#pragma unroll
    for (int i = 0; i < 32; i += 8)
        tile[threadIdx.y + i][threadIdx.x] = src[(size_t)(y + i) * D + x];
    __syncthreads();
    int tx = blockIdx.y * 32 + threadIdx.x;
    int ty = blockIdx.x * 32 + threadIdx.y;
#pragma unroll
    for (int i = 0; i < 32; i += 8)
        dst[(size_t)(ty + i) * D + tx] = tile[threadIdx.x][threadIdx.y + i];
}

// ---------------------------------------------------------------------------
// K1/K4: tf32 mma.sync GEMM, register-prefetch pipelined.
// Y[m,n] = A[m,:] . Bt[n,:]  (+bias[, +resid])
// mode 0: proj layout; z=0,1 -> qh/kh rows; z=2 -> V written TRANSPOSED to g_vt.
// mode 1: flat output + residual add (fc).
// ---------------------------------------------------------------------------
__global__ __launch_bounds__(256, 2) void gemm_mma_kernel(
    const float* __restrict__ A0, const float* __restrict__ A1,
    const float* __restrict__ A2, const float* __restrict__ Bt,
    const float* __restrict__ bias, const float* __restrict__ resid,
    float* __restrict__ O0, float* __restrict__ O1, float* __restrict__ O2,
    int mode)
{
    extern __shared__ uint32_t smu[];
    uint32_t* As = smu;                 // [128][36]
    uint32_t* Bs = smu + 128 * GST;     // [128][36]

    const int tid  = threadIdx.x;
    const int wid  = tid >> 5, lane = tid & 31;
    const int g    = lane >> 2, tq = lane & 3;
    const int wm   = (wid >> 2) * 64;
    const int wn   = (wid & 3) * 32;
    const int n0   = blockIdx.x * 128;
    const int m0   = blockIdx.y * 128;

    const float* Ap;
    float* Op;
    if (blockIdx.z == 0)      { Ap = A0; Op = O0; }
    else if (blockIdx.z == 1) { Ap = A1; Op = O1; }
    else                      { Ap = A2; Op = O2; }

    // fill mapping: 1024 float4 per [128][32] tile -> 4 per thread
    const int frow = tid >> 3, fc4 = tid & 7;      // base for i-th: row = frow + i*32

    float acc[4][4][4];
#pragma unroll
    for (int i = 0; i < 4; i++)
#pragma unroll
        for (int j = 0; j < 4; j++)
#pragma unroll
            for (int r = 0; r < 4; r++) acc[i][j][r] = 0.f;

    // prefetch chunk 0
    float4 pa[4], pb[4];
#pragma unroll
    for (int i = 0; i < 4; i++) {
        int row = frow + i * 32;
        pa[i] = *(const float4*)(Ap + (size_t)(m0 + row) * D + fc4 * 4);
        pb[i] = *(const float4*)(Bt + (size_t)(n0 + row) * D + fc4 * 4);
    }

    for (int kt = 0; kt < D; kt += KC) {
        // store prefetched chunk (cvt to tf32)
#pragma unroll
        for (int i = 0; i < 4; i++) {
            int row = frow + i * 32;
            uint32_t* ad = &As[row * GST + fc4 * 4];
            ad[0] = f2tf32(pa[i].x); ad[1] = f2tf32(pa[i].y);
            ad[2] = f2tf32(pa[i].z); ad[3] = f2tf32(pa[i].w);
            uint32_t* bd = &Bs[row * GST + fc4 * 4];
            bd[0] = f2tf32(pb[i].x); bd[1] = f2tf32(pb[i].y);
            bd[2] = f2tf32(pb[i].z); bd[3] = f2tf32(pb[i].w);
        }
        __syncthreads();

        // issue loads for next chunk (latency covered by MMA below)
        if (kt + KC < D) {
#pragma unroll
            for (int i = 0; i < 4; i++) {
                int row = frow + i * 32;
                pa[i] = *(const float4*)(Ap + (size_t)(m0 + row) * D + kt + KC + fc4 * 4);
                pb[i] = *(const float4*)(Bt + (size_t)(n0 + row) * D + kt + KC + fc4 * 4);
            }
        }

#pragma unroll
        for (int ks = 0; ks < KC / 8; ks++) {
            const int kk = ks * 8;
            uint32_t a[4][4], b[4][2];
#pragma unroll
            for (int mf = 0; mf < 4; mf++) {
                const int row = wm + mf * 16 + g;
                a[mf][0] = As[row * GST + kk + tq];
                a[mf][1] = As[(row + 8) * GST + kk + tq];
                a[mf][2] = As[row * GST + kk + tq + 4];
                a[mf][3] = As[(row + 8) * GST + kk + tq + 4];
            }
#pragma unroll
            for (int nf = 0; nf < 4; nf++) {
                const int col = wn + nf * 8 + g;
                b[nf][0] = Bs[col * GST + kk + tq];
                b[nf][1] = Bs[col * GST + kk + tq + 4];
            }
#pragma unroll
            for (int mf = 0; mf < 4; mf++)
#pragma unroll
                for (int nf = 0; nf < 4; nf++)
                    mma_tf32(acc[mf][nf], a[mf], b[nf]);
        }
        __syncthreads();
    }

#pragma unroll
    for (int mf = 0; mf < 4; mf++) {
#pragma unroll
        for (int nf = 0; nf < 4; nf++) {
            const int m = m0 + wm + mf * 16 + g;
            const int n = n0 + wn + nf * 8 + tq * 2;
            float bx = bias[n], by = bias[n + 1];
#pragma unroll
            for (int half = 0; half < 2; half++) {
                const int mm = m + half * 8;
                float vx = acc[mf][nf][half * 2 + 0] + bx;
                float vy = acc[mf][nf][half * 2 + 1] + by;
                if (mode == 0) {
                    const int h = n >> 6, dk = n & 63;
                    const int bb_ = mm >> 11, s = mm & 2047;
                    if (blockIdx.z == 2) {
                        float* vtb = &g_vt[(((size_t)bb_ * H + h) * DK + dk) * S + s];
                        vtb[0] = vx;
                        vtb[S] = vy;
                    } else {
                        float2* p = (float2*)&Op[(((size_t)bb_ * H + h) * S + s) * DK + dk];
                        *p = make_float2(vx, vy);
                    }
                } else {
                    const float* rr = resid + (size_t)mm * D + n;
                    float2 r2 = *(const float2*)rr;
                    float2* p = (float2*)&Op[(size_t)mm * D + n];
                    *p = make_float2(vx + r2.x, vy + r2.y);
                }
            }
        }
    }
}

// ---------------------------------------------------------------------------
// K2: attention via tf32 mma.sync, register-prefetch pipelined K/V tiles.
// grid (16 q-tiles, 64 bh), block 256. Warp grid 4x2.
// Per 64-key tile: STS prefetched K/V -> sync -> S=Q·K^T -> exp (rowsum,
// E to gmem, P to smem) -> prefetch next K/V -> sync -> ctx += P·V -> sync.
// ---------------------------------------------------------------------------
__global__ __launch_bounds__(256, 2) void attn_mma_kernel(float* __restrict__ attn_out)
{
    extern __shared__ uint32_t smu[];
    uint32_t* Qs = smu + AQ_OFF;
    uint32_t* Ks = smu + AK_OFF;
    uint32_t* Vt = smu + AV_OFF;
    uint32_t* Ps = smu + AP_OFF;
    float* rs    = (float*)(smu + ARS_OFF);
    float* sinv  = (float*)(smu + AIV_OFF);

    const int bh = blockIdx.y;
    const int q0 = blockIdx.x * 128;
    const int tid = threadIdx.x;
    const int wid = tid >> 5, lane = tid & 31;
    const int g = lane >> 2, tq = lane & 3;
    const int wm = (wid >> 1) * 32;
    const int wn = (wid & 1) * 32;
    const float scale = 0.125f;

    const int frow = tid >> 4, fc4 = tid & 15;   // K/V fill: row = frow + i*16

    // Q tile: 128 rows x 64 d -> Qs (tf32, pre-scaled)
#pragma unroll
    for (int i = 0; i < 8; i++) {
        int f4 = tid + i * 256;
        int row = f4 >> 4, c4 = f4 & 15;
        float4 qv = *(const float4*)&g_qh[((size_t)bh * S + q0 + row) * DK + c4 * 4];
        uint32_t* qd = &Qs[row * 68 + c4 * 4];
        qd[0] = f2tf32(qv.x * scale); qd[1] = f2tf32(qv.y * scale);
        qd[2] = f2tf32(qv.z * scale); qd[3] = f2tf32(qv.w * scale);
    }

    // prefetch K/V tile 0
    float4 pk[4], pv[4];
#pragma unroll
    for (int i = 0; i < 4; i++) {
        int row = frow + i * 16;
        pk[i] = *(const float4*)&g_kh[((size_t)bh * S + row) * DK + fc4 * 4];
        pv[i] = *(const float4*)&g_vt[((size_t)bh * DK + row) * S + fc4 * 4];
    }

    float cacc[2][4][4];
    float rsum[2][2] = {{0.f, 0.f}, {0.f, 0.f}};
#pragma unroll
    for (int mf = 0; mf < 2; mf++)
#pragma unroll
        for (int nf = 0; nf < 4; nf++)
#pragma unroll
            for (int r = 0; r < 4; r++) cacc[mf][nf][r] = 0.f;

    for (int kt = 0; kt < S / 64; kt++) {
        const int k0 = kt * 64;
        // store prefetched K/V tiles (tf32)
#pragma unroll
        for (int i = 0; i < 4; i++) {
            int row = frow + i * 16;
            uint32_t* kd = &Ks[row * 68 + fc4 * 4];
            kd[0] = f2tf32(pk[i].x); kd[1] = f2tf32(pk[i].y);
            kd[2] = f2tf32(pk[i].z); kd[3] = f2tf32(pk[i].w);
            uint32_t* vd = &Vt[row * 68 + fc4 * 4];
            vd[0] = f2tf32(pv[i].x); vd[1] = f2tf32(pv[i].y);
            vd[2] = f2tf32(pv[i].z); vd[3] = f2tf32(pv[i].w);
        }
        __syncthreads();

        // S = Q·K^T  (k = d, 8 steps)
        float sacc[2][4][4];
#pragma unroll
        for (int mf = 0; mf < 2; mf++)
#pragma unroll
            for (int nf = 0; nf < 4; nf++)
#pragma unroll
                for (int r = 0; r < 4; r++) sacc[mf][nf][r] = 0.f;
#pragma unroll
        for (int ks = 0; ks < 8; ks++) {
            const int kk = ks * 8;
            uint32_t a[2][4], b[4][2];
#pragma unroll
            for (int mf = 0; mf < 2; mf++) {
                const int row = wm + mf * 16 + g;
                a[mf][0] = Qs[row * 68 + kk + tq];
                a[mf][1] = Qs[(row + 8) * 68 + kk + tq];
                a[mf][2] = Qs[row * 68 + kk + tq + 4];
                a[mf][3] = Qs[(row + 8) * 68 + kk + tq + 4];
            }
#pragma unroll
            for (int nf = 0; nf < 4; nf++) {
                const int col = wn + nf * 8 + g;
                b[nf][0] = Ks[col * 68 + kk + tq];
                b[nf][1] = Ks[col * 68 + kk + tq + 4];
            }
#pragma unroll
            for (int mf = 0; mf < 2; mf++)
#pragma unroll
                for (int nf = 0; nf < 4; nf++)
                    mma_tf32(sacc[mf][nf], a[mf], b[nf]);
        }

        // exp, rowsum, E -> gmem (unnormalized), P -> smem (tf32)
#pragma unroll
        for (int mf = 0; mf < 2; mf++) {
            const int r0 = wm + mf * 16 + g;
#pragma unroll
            for (int nf = 0; nf < 4; nf++) {
                const int c0 = wn + nf * 8 + tq * 2;
                float e00 = fast_exp(sacc[mf][nf][0]);
                float e01 = fast_exp(sacc[mf][nf][1]);
                float e10 = fast_exp(sacc[mf][nf][2]);
                float e11 = fast_exp(sacc[mf][nf][3]);
                rsum[mf][0] += e00 + e01;
                rsum[mf][1] += e10 + e11;
                *(float2*)&attn_out[((size_t)bh * S + q0 + r0) * S + k0 + c0] =
                    make_float2(e00, e01);
                *(float2*)&attn_out[((size_t)bh * S + q0 + r0 + 8) * S + k0 + c0] =
                    make_float2(e10, e11);
                Ps[r0 * 68 + c0]       = f2tf32(e00);
                Ps[r0 * 68 + c0 + 1]   = f2tf32(e01);
                Ps[(r0 + 8) * 68 + c0]     = f2tf32(e10);
                Ps[(r0 + 8) * 68 + c0 + 1] = f2tf32(e11);
            }
        }

        // issue next tile's K/V loads (sacc now dead; covered by P·V below)
        if (kt + 1 < S / 64) {
            const int nk0 = k0 + 64;
#pragma unroll
            for (int i = 0; i < 4; i++) {
                int row = frow + i * 16;
                pk[i] = *(const float4*)&g_kh[((size_t)bh * S + nk0 + row) * DK + fc4 * 4];
                pv[i] = *(const float4*)&g_vt[((size_t)bh * DK + row) * S + nk0 + fc4 * 4];
            }
        }
        __syncthreads();

        // ctx += P·V   (k = key, 8 steps; B = Vt[d][key])
#pragma unroll
        for (int ks = 0; ks < 8; ks++) {
            const int kk = ks * 8;
            uint32_t a[2][4], b[4][2];
#pragma unroll
            for (int mf = 0; mf < 2; mf++) {
                const int row = wm + mf * 16 + g;
                a[mf][0] = Ps[row * 68 + kk + tq];
                a[mf][1] = Ps[(row + 8) * 68 + kk + tq];
                a[mf][2] = Ps[row * 68 + kk + tq + 4];
                a[mf][3] = Ps[(row + 8) * 68 + kk + tq + 4];
            }
#pragma unroll
            for (int nf = 0; nf < 4; nf++) {
                const int col = wn + nf * 8 + g;
                b[nf][0] = Vt[col * 68 + kk + tq];
                b[nf][1] = Vt[col * 68 + kk + tq + 4];
            }
#pragma unroll
            for (int mf = 0; mf < 2; mf++)
#pragma unroll
                for (int nf = 0; nf < 4; nf++)
                    mma_tf32(cacc[mf][nf], a[mf], b[nf]);
        }
        __syncthreads();
    }

    // rowsum: reduce across tq lanes (same g), publish per warp-column
#pragma unroll
    for (int mf = 0; mf < 2; mf++)
#pragma unroll
        for (int hh = 0; hh < 2; hh++) {
            float v = rsum[mf][hh];
            v += __shfl_xor_sync(0xffffffffu, v, 1);
            v += __shfl_xor_sync(0xffffffffu, v, 2);
            rsum[mf][hh] = v;
        }
    if (tq == 0) {
#pragma unroll
        for (int mf = 0; mf < 2; mf++)
#pragma unroll
            for (int hh = 0; hh < 2; hh++)
                rs[(wid & 1) * 128 + wm + mf * 16 + hh * 8 + g] = rsum[mf][hh];
    }
    __syncthreads();
    if (tid < 128) {
        float iv = 1.0f / (rs[tid] + rs[128 + tid]);
        g_rinv[(size_t)bh * S + q0 + tid] = iv;
        sinv[tid] = iv;
    }
    __syncthreads();

    // scaled ctx -> g_ctx[(b*S+s)*D + h*64 + d]
    const int b_ = bh >> 4, h_ = bh & 15;
#pragma unroll
    for (int mf = 0; mf < 2; mf++) {
        const int r0 = wm + mf * 16 + g;
        const float iv0 = sinv[r0], iv1 = sinv[r0 + 8];
#pragma unroll
        for (int nf = 0; nf < 4; nf++) {
            const int c0 = wn + nf * 8 + tq * 2;
            *(float2*)&g_ctx[((size_t)b_ * S + q0 + r0) * D + h_ * DK + c0] =
                make_float2(cacc[mf][nf][0] * iv0, cacc[mf][nf][1] * iv0);
            *(float2*)&g_ctx[((size_t)b_ * S + q0 + r0 + 8) * D + h_ * DK + c0] =
                make_float2(cacc[mf][nf][2] * iv1, cacc[mf][nf][3] * iv1);
        }
    }
}

// ---------------------------------------------------------------------------
// K3: normalize attn in place:  attn[row][*] *= rinv[row]
// ---------------------------------------------------------------------------
__global__ __launch_bounds__(256) void attn_scale_kernel(float* __restrict__ attn)
{
    size_t idx4 = (size_t)blockIdx.x * blockDim.x + threadIdx.x;
    size_t row  = idx4 >> 9;
    float inv = g_rinv[row];
    float4* p = (float4*)attn + idx4;
    float4 v = *p;
    v.x *= inv; v.y *= inv; v.z *= inv; v.w *= inv;
    *p = v;
}

// ---------------------------------------------------------------------------
// K5: LayerNorm over last dim (1024). One block (256 thr) per row.
// ---------------------------------------------------------------------------
__global__ __launch_bounds__(256) void ln_kernel(
    const float* __restrict__ gamma, const float* __restrict__ beta,
    float* __restrict__ out)
{
    __shared__ float s1[8], s2[8];
    __shared__ float sm_mean, sm_rstd;
    const int row = blockIdx.x;
    const int t   = threadIdx.x;
    const float* x = g_x + (size_t)row * D;

    float4 v = *(const float4*)(x + t * 4);
    float sum = v.x + v.y + v.z + v.w;
    float sq  = v.x * v.x + v.y * v.y + v.z * v.z + v.w * v.w;
#pragma unroll
    for (int m = 16; m >= 1; m >>= 1) {
        sum += __shfl_xor_sync(0xffffffffu, sum, m);
        sq  += __shfl_xor_sync(0xffffffffu, sq, m);
    }
    const int warp = t >> 5, lane = t & 31;
    if (lane == 0) { s1[warp] = sum; s2[warp] = sq; }
    __syncthreads();
    if (t == 0) {
        float a = 0.f, c = 0.f;
#pragma unroll
        for (int w = 0; w < 8; w++) { a += s1[w]; c += s2[w]; }
        float mean = a * (1.0f / D);
        float var  = c * (1.0f / D) - mean * mean;
        sm_mean = mean;
        sm_rstd = rsqrtf(var + 1e-6f);
    }
    __syncthreads();
    const float mean = sm_mean, r = sm_rstd;
    float4 g4 = *(const float4*)(gamma + t * 4);
    float4 b4 = *(const float4*)(beta + t * 4);
    float4 o;
    o.x = (v.x - mean) * r * g4.x + b4.x;
    o.y = (v.y - mean) * r * g4.y + b4.y;
    o.z = (v.z - mean) * r * g4.z + b4.z;
    o.w = (v.w - mean) * r * g4.w + b4.w;
    *(float4*)(out + (size_t)row * D + t * 4) = o;
}

// ---------------------------------------------------------------------------
extern "C" void kernel_launch(void* const* d_in, const int* in_sizes, int n_in,
                              void* d_out, int out_size)
{
    const float* q     = (const float*)d_in[0];
    const float* k     = (const float*)d_in[1];
    const float* v     = (const float*)d_in[2];
    const float* Wq    = (const float*)d_in[3];
    const float* bq    = (const float*)d_in[4];
    const float* Wfc   = (const float*)d_in[5];
    const float* bfc   = (const float*)d_in[6];
    const float* gamma = (const float*)d_in[7];
    const float* beta  = (const float*)d_in[8];

    float* out_x    = (float*)d_out;
    float* out_attn = out_x + X_ELEMS;

    cudaFuncSetAttribute(attn_mma_kernel,
                         cudaFuncAttributeMaxDynamicSharedMemorySize, ATTN_SMEM);

    float *wqt_p, *wfct_p, *qh_p, *kh_p, *vt_p, *ctx_p, *x_p;
    cudaGetSymbolAddress((void**)&wqt_p,  g_wqt);
    cudaGetSymbolAddress((void**)&wfct_p, g_wfct);
    cudaGetSymbolAddress((void**)&qh_p,   g_qh);
    cudaGetSymbolAddress((void**)&kh_p,   g_kh);
    cudaGetSymbolAddress((void**)&vt_p,   g_vt);
    cudaGetSymbolAddress((void**)&ctx_p,  g_ctx);
    cudaGetSymbolAddress((void**)&x_p,    g_x);

    transpose_kernel<<<dim3(32, 32, 2), dim3(32, 8)>>>(Wq, Wfc);
    gemm_mma_kernel<<<dim3(8, 64, 3), 256, GEMM_SMEM>>>(
        q, k, v, wqt_p, bq, nullptr, qh_p, kh_p, vt_p, 0);
    attn_mma_kernel<<<dim3(16, 64), 256, ATTN_SMEM>>>(out_attn);
    attn_scale_kernel<<<(unsigned)(ATTN_ELEMS / 4 / 256), 256>>>(out_attn);
    gemm_mma_kernel<<<dim3(8, 64, 1), 256, GEMM_SMEM>>>(
        ctx_p, ctx_p, ctx_p, wfct_p, bfc, q, x_p, x_p, x_p, 1);
    ln_kernel<<<B * S, 256>>>(gamma, beta, out_x);
}

// round 6
// speedup vs baseline: 1.4810x; 1.4810x over previous
#include <cuda_runtime.h>
#include <cstdint>

// ---------------------------------------------------------------------------
// MultiHeadAttention (B=4, S=2048, D=1024, H=16, DK=64).
// Round 6: R4 structure + cp.async pipelining (zero register cost).
//  - dense GEMMs: 2-stage cp.async smem pipeline, cvt-at-fragment-load
//  - attention:   cp.async K/V issued into dead phases, single buffers
// tf32 mma.sync everywhere; polynomial exp on FMA pipe.
// Output layout: d_out = [ x (8,388,608 f32) | attn (268,435,456 f32) ]
// ---------------------------------------------------------------------------

namespace {
constexpr int B  = 4;
constexpr int S  = 2048;
constexpr int D  = 1024;
constexpr int H  = 16;
constexpr int DK = 64;
constexpr size_t QH_ELEMS   = (size_t)B * H * S * DK;        // 8,388,608
constexpr size_t X_ELEMS    = (size_t)B * S * D;             // 8,388,608
constexpr size_t ATTN_ELEMS = (size_t)B * H * S * (size_t)S; // 268,435,456

// dense-GEMM tiling: CTA 128x128, warp 64x32 (2x4 warps), K-chunk 32,
// two cp.async stages. Tile stride 36 words (=4 mod 32 -> conflict-free).
constexpr int KC  = 32;
constexpr int NCH = D / KC;                 // 32 chunks
constexpr int GST = 36;
constexpr int GTILE = 128 * GST;            // words per tile
constexpr int GEMM_SMEM = 4 * GTILE * 4;    // 73,728 B (As0,Bs0,As1,Bs1)

// attention smem layout (uint32 words)
constexpr int AQ_OFF = 0;                  // Qs[128][68] (tf32)
constexpr int AK_OFF = AQ_OFF + 128 * 68;  // Ks[64][68]  (raw fp32)
constexpr int AV_OFF = AK_OFF + 64 * 68;   // Vt[64][68]  (raw fp32; d rows, key cols)
constexpr int AP_OFF = AV_OFF + 64 * 68;   // Ps[128][68] (tf32)
constexpr int ARS_OFF = AP_OFF + 128 * 68; // rs[2][128] floats
constexpr int AIV_OFF = ARS_OFF + 256;     // sinv[128] floats
constexpr int ATTN_SMEM = (AIV_OFF + 128) * 4;   // 105,984 B
}

// Scratch (allocation-free rule: __device__ globals)
__device__ float g_qh[QH_ELEMS];
__device__ float g_kh[QH_ELEMS];
__device__ float g_vt[QH_ELEMS];           // V transposed: [bh][d][s]
__device__ float g_ctx[X_ELEMS];
__device__ float g_x[X_ELEMS];
__device__ float g_rinv[(size_t)B * H * S];
__device__ float g_wqt[(size_t)D * D];     // Wq^T  [N][K]
__device__ float g_wfct[(size_t)D * D];    // Wfc^T [N][K]

// ---------------------------------------------------------------------------
// helpers
// ---------------------------------------------------------------------------
__device__ __forceinline__ uint32_t smem_to_u32(const void* p) {
    uint32_t a;
    asm("{ .reg .u64 t; cvta.to.shared.u64 t, %1; cvt.u32.u64 %0, t; }"
        : "=r"(a) : "l"(p));
    return a;
}
__device__ __forceinline__ uint32_t f2tf32(float x) {
    uint32_t r;
    asm("cvt.rna.tf32.f32 %0, %1;" : "=r"(r) : "f"(x));
    return r;
}
__device__ __forceinline__ uint32_t tf32b(uint32_t rawbits) {
    return f2tf32(__uint_as_float(rawbits));
}
__device__ __forceinline__ void mma_tf32(float* d, const uint32_t* a, const uint32_t* b) {
    asm volatile(
        "mma.sync.aligned.m16n8k8.row.col.f32.tf32.tf32.f32 "
        "{%0,%1,%2,%3}, {%4,%5,%6,%7}, {%8,%9}, {%0,%1,%2,%3};"
        : "+f"(d[0]), "+f"(d[1]), "+f"(d[2]), "+f"(d[3])
        : "r"(a[0]), "r"(a[1]), "r"(a[2]), "r"(a[3]), "r"(b[0]), "r"(b[1]));
}
__device__ __forceinline__ void cp16(uint32_t dst, const void* src) {
    asm volatile("cp.async.cg.shared.global [%0], [%1], 16;" :: "r"(dst), "l"(src));
}
__device__ __forceinline__ void cp8(uint32_t dst, const void* src) {
    asm volatile("cp.async.ca.shared.global [%0], [%1], 8;" :: "r"(dst), "l"(src));
}
__device__ __forceinline__ void cp_commit() {
    asm volatile("cp.async.commit_group;" ::: "memory");
}
__device__ __forceinline__ void cp_wait0() {
    asm volatile("cp.async.wait_group 0;" ::: "memory");
}
__device__ __forceinline__ void cp_wait1() {
    asm volatile("cp.async.wait_group 1;" ::: "memory");
}
// exp via FMA pipe: magic-number range reduction + deg-5 poly (rel err ~2e-6).
__device__ __forceinline__ float fast_exp(float x) {
    const float L2E = 1.4426950408889634f;
    float t = fmaf(x, L2E, 12582912.0f);
    float n = t - 12582912.0f;
    float f = fmaf(x, L2E, -n);
    float p = 0.0013333558f;
    p = fmaf(p, f, 0.0096181291f);
    p = fmaf(p, f, 0.0555041087f);
    p = fmaf(p, f, 0.2402265069f);
    p = fmaf(p, f, 0.6931471806f);
    p = fmaf(p, f, 1.0f);
    return __int_as_float(__float_as_int(p) + (__float_as_int(t) << 23));
}

// ---------------------------------------------------------------------------
// K0: transpose Wq and Wfc once -> g_wqt / g_wfct  (W is [K=1024][N=1024])
// ---------------------------------------------------------------------------
__global__ __launch_bounds__(256) void transpose_kernel(
    const float* __restrict__ Wq, const float* __restrict__ Wfc)
{
    __shared__ float tile[32][33];
    const float* src = blockIdx.z ? Wfc : Wq;
    float*       dst = blockIdx.z ? g_wfct : g_wqt;
    int x = blockIdx.x * 32 + threadIdx.x;
    int y = blockIdx.y * 32 + threadIdx.y;
#pragma unroll
    for (int i = 0; i < 32; i += 8)
        tile[threadIdx.y + i][threadIdx.x] = src[(size_t)(y + i) * D + x];
    __syncthreads();
    int tx = blockIdx.y * 32 + threadIdx.x;
    int ty = blockIdx.x * 32 + threadIdx.y;
#pragma unroll
    for (int i = 0; i < 32; i += 8)
        dst[(size_t)(ty + i) * D + tx] = tile[threadIdx.x][threadIdx.y + i];
}

// ---------------------------------------------------------------------------
// K1/K4: tf32 mma.sync GEMM, 2-stage cp.async pipeline.
// Y[m,n] = A[m,:] . Bt[n,:]  (+bias[, +resid])
// mode 0: proj layout; z=0,1 -> qh/kh rows; z=2 -> V written TRANSPOSED to g_vt.
// mode 1: flat output + residual add (fc).
// Smem holds raw fp32; cvt.rna applied at fragment load (numerics == R4).
// ---------------------------------------------------------------------------
__global__ __launch_bounds__(256) void gemm_mma_kernel(
    const float* __restrict__ A0, const float* __restrict__ A1,
    const float* __restrict__ A2, const float* __restrict__ Bt,
    const float* __restrict__ bias, const float* __restrict__ resid,
    float* __restrict__ O0, float* __restrict__ O1, float* __restrict__ O2,
    int mode)
{
    extern __shared__ uint32_t smu[];
    const uint32_t smem_u = smem_to_u32(smu);

    const int tid  = threadIdx.x;
    const int wid  = tid >> 5, lane = tid & 31;
    const int g    = lane >> 2, tq = lane & 3;
    const int wm   = (wid >> 2) * 64;
    const int wn   = (wid & 3) * 32;
    const int n0   = blockIdx.x * 128;
    const int m0   = blockIdx.y * 128;

    const float* Ap;
    float* Op;
    if (blockIdx.z == 0)      { Ap = A0; Op = O0; }
    else if (blockIdx.z == 1) { Ap = A1; Op = O1; }
    else                      { Ap = A2; Op = O2; }

    float acc[4][4][4];
#pragma unroll
    for (int i = 0; i < 4; i++)
#pragma unroll
        for (int j = 0; j < 4; j++)
#pragma unroll
            for (int r = 0; r < 4; r++) acc[i][j][r] = 0.f;

    // prologue: issue chunks 0 (stage 0) and 1 (stage 1)
#pragma unroll
    for (int c0 = 0; c0 < 2; c0++) {
        const int kt = c0 * KC;
        const uint32_t sbase = smem_u + (uint32_t)(c0 * 2 * GTILE) * 4;
#pragma unroll
        for (int j = 0; j < 8; j++) {
            int idx = tid + j * 256;          // 2048 8B-chunks per tile
            int row = idx >> 4, ch = idx & 15;
            uint32_t off = (uint32_t)(row * GST + ch * 2) * 4;
            cp8(sbase + off,             Ap + (size_t)(m0 + row) * D + kt + ch * 2);
            cp8(sbase + off + GTILE * 4, Bt + (size_t)(n0 + row) * D + kt + ch * 2);
        }
        cp_commit();
    }

    for (int c = 0; c < NCH; c++) {
        const int st = c & 1;
        if (c + 1 < NCH) cp_wait1(); else cp_wait0();
        __syncthreads();

        const uint32_t* As = smu + st * 2 * GTILE;
        const uint32_t* Bs = As + GTILE;

#pragma unroll
        for (int ks = 0; ks < KC / 8; ks++) {
            const int kk = ks * 8;
            uint32_t a[4][4], b[4][2];
#pragma unroll
            for (int mf = 0; mf < 4; mf++) {
                const int row = wm + mf * 16 + g;
                a[mf][0] = tf32b(As[row * GST + kk + tq]);
                a[mf][1] = tf32b(As[(row + 8) * GST + kk + tq]);
                a[mf][2] = tf32b(As[row * GST + kk + tq + 4]);
                a[mf][3] = tf32b(As[(row + 8) * GST + kk + tq + 4]);
            }
#pragma unroll
            for (int nf = 0; nf < 4; nf++) {
                const int col = wn + nf * 8 + g;
                b[nf][0] = tf32b(Bs[col * GST + kk + tq]);
                b[nf][1] = tf32b(Bs[col * GST + kk + tq + 4]);
            }
#pragma unroll
            for (int mf = 0; mf < 4; mf++)
#pragma unroll
                for (int nf = 0; nf < 4; nf++)
                    mma_tf32(acc[mf][nf], a[mf], b[nf]);
        }
        __syncthreads();

        // refill this stage with chunk c+2 (overlaps chunk c+1's compute)
        if (c + 2 < NCH) {
            const int kt = (c + 2) * KC;
            const uint32_t sbase = smem_u + (uint32_t)(st * 2 * GTILE) * 4;
#pragma unroll
            for (int j = 0; j < 8; j++) {
                int idx = tid + j * 256;
                int row = idx >> 4, ch = idx & 15;
                uint32_t off = (uint32_t)(row * GST + ch * 2) * 4;
                cp8(sbase + off,             Ap + (size_t)(m0 + row) * D + kt + ch * 2);
                cp8(sbase + off + GTILE * 4, Bt + (size_t)(n0 + row) * D + kt + ch * 2);
            }
            cp_commit();
        }
    }

#pragma unroll
    for (int mf = 0; mf < 4; mf++) {
#pragma unroll
        for (int nf = 0; nf < 4; nf++) {
            const int m = m0 + wm + mf * 16 + g;
            const int n = n0 + wn + nf * 8 + tq * 2;
            float bx = bias[n], by = bias[n + 1];
#pragma unroll
            for (int half = 0; half < 2; half++) {
                const int mm = m + half * 8;
                float vx = acc[mf][nf][half * 2 + 0] + bx;
                float vy = acc[mf][nf][half * 2 + 1] + by;
                if (mode == 0) {
                    const int h = n >> 6, dk = n & 63;
                    const int bb_ = mm >> 11, s = mm & 2047;
                    if (blockIdx.z == 2) {
                        float* vtb = &g_vt[(((size_t)bb_ * H + h) * DK + dk) * S + s];
                        vtb[0] = vx;
                        vtb[S] = vy;
                    } else {
                        float2* p = (float2*)&Op[(((size_t)bb_ * H + h) * S + s) * DK + dk];
                        *p = make_float2(vx, vy);
                    }
                } else {
                    const float* rr = resid + (size_t)mm * D + n;
                    float2 r2 = *(const float2*)rr;
                    float2* p = (float2*)&Op[(size_t)mm * D + n];
                    *p = make_float2(vx + r2.x, vy + r2.y);
                }
            }
        }
    }
}

// ---------------------------------------------------------------------------
// K2: attention via tf32 mma.sync, cp.async K/V slid into dead phases.
// grid (16 q-tiles, 64 bh), block 256. Warp grid 4x2.
// Per 64-key tile:
//   wait K(t) -> sync -> QK (cvt on Ks frags) -> exp/rowsum/E-out/Ps
//   wait V(t) -> sync -> issue K(t+1) -> PV (cvt on Vt frags)
//   sync -> issue V(t+1)
// ---------------------------------------------------------------------------
__global__ __launch_bounds__(256, 2) void attn_mma_kernel(float* __restrict__ attn_out)
{
    extern __shared__ uint32_t smu[];
    uint32_t* Qs = smu + AQ_OFF;
    uint32_t* Ks = smu + AK_OFF;
    uint32_t* Vt = smu + AV_OFF;
    uint32_t* Ps = smu + AP_OFF;
    float* rs    = (float*)(smu + ARS_OFF);
    float* sinv  = (float*)(smu + AIV_OFF);
    const uint32_t smem_u = smem_to_u32(smu);
    const uint32_t ks_u = smem_u + AK_OFF * 4;
    const uint32_t vt_u = smem_u + AV_OFF * 4;

    const int bh = blockIdx.y;
    const int q0 = blockIdx.x * 128;
    const int tid = threadIdx.x;
    const int wid = tid >> 5, lane = tid & 31;
    const int g = lane >> 2, tq = lane & 3;
    const int wm = (wid >> 1) * 32;
    const int wn = (wid & 1) * 32;
    const float scale = 0.125f;

    // fill mapping for K/V tiles: 1024 float4 per tile -> 4 per thread
    const int frow = tid >> 4, fc4 = tid & 15;     // rows frow + i*16

    // Q tile: 128 rows x 64 d -> Qs (tf32, pre-scaled)
#pragma unroll
    for (int i = 0; i < 8; i++) {
        int f4 = tid + i * 256;
        int row = f4 >> 4, c4 = f4 & 15;
        float4 qv = *(const float4*)&g_qh[((size_t)bh * S + q0 + row) * DK + c4 * 4];
        uint32_t* qd = &Qs[row * 68 + c4 * 4];
        qd[0] = f2tf32(qv.x * scale); qd[1] = f2tf32(qv.y * scale);
        qd[2] = f2tf32(qv.z * scale); qd[3] = f2tf32(qv.w * scale);
    }

    // prologue: issue K(0) then V(0) as separate groups
#pragma unroll
    for (int i = 0; i < 4; i++) {
        int row = frow + i * 16;
        cp16(ks_u + (uint32_t)(row * 68 + fc4 * 4) * 4,
             &g_kh[((size_t)bh * S + row) * DK + fc4 * 4]);
    }
    cp_commit();
#pragma unroll
    for (int i = 0; i < 4; i++) {
        int row = frow + i * 16;
        cp16(vt_u + (uint32_t)(row * 68 + fc4 * 4) * 4,
             &g_vt[((size_t)bh * DK + row) * S + fc4 * 4]);
    }
    cp_commit();

    float cacc[2][4][4];
    float rsum[2][2] = {{0.f, 0.f}, {0.f, 0.f}};
#pragma unroll
    for (int mf = 0; mf < 2; mf++)
#pragma unroll
        for (int nf = 0; nf < 4; nf++)
#pragma unroll
            for (int r = 0; r < 4; r++) cacc[mf][nf][r] = 0.f;

    for (int kt = 0; kt < S / 64; kt++) {
        const int k0 = kt * 64;

        cp_wait1();            // K(kt) arrived (V(kt) may still be in flight)
        __syncthreads();       // publish K to all threads (and Qs on iter 0)

        // S = Q·K^T  (k = d, 8 steps); cvt.rna on K fragments
        float sacc[2][4][4];
#pragma unroll
        for (int mf = 0; mf < 2; mf++)
#pragma unroll
            for (int nf = 0; nf < 4; nf++)
#pragma unroll
                for (int r = 0; r < 4; r++) sacc[mf][nf][r] = 0.f;
#pragma unroll
        for (int ks = 0; ks < 8; ks++) {
            const int kk = ks * 8;
            uint32_t a[2][4], b[4][2];
#pragma unroll
            for (int mf = 0; mf < 2; mf++) {
                const int row = wm + mf * 16 + g;
                a[mf][0] = Qs[row * 68 + kk + tq];
                a[mf][1] = Qs[(row + 8) * 68 + kk + tq];
                a[mf][2] = Qs[row * 68 + kk + tq + 4];
                a[mf][3] = Qs[(row + 8) * 68 + kk + tq + 4];
            }
#pragma unroll
            for (int nf = 0; nf < 4; nf++) {
                const int col = wn + nf * 8 + g;
                b[nf][0] = tf32b(Ks[col * 68 + kk + tq]);
                b[nf][1] = tf32b(Ks[col * 68 + kk + tq + 4]);
            }
#pragma unroll
            for (int mf = 0; mf < 2; mf++)
#pragma unroll
                for (int nf = 0; nf < 4; nf++)
                    mma_tf32(sacc[mf][nf], a[mf], b[nf]);
        }

        // exp, rowsum, E -> gmem (unnormalized), P -> smem (tf32)
#pragma unroll
        for (int mf = 0; mf < 2; mf++) {
            const int r0 = wm + mf * 16 + g;
#pragma unroll
            for (int nf = 0; nf < 4; nf++) {
                const int c0 = wn + nf * 8 + tq * 2;
                float e00 = fast_exp(sacc[mf][nf][0]);
                float e01 = fast_exp(sacc[mf][nf][1]);
                float e10 = fast_exp(sacc[mf][nf][2]);
                float e11 = fast_exp(sacc[mf][nf][3]);
                rsum[mf][0] += e00 + e01;
                rsum[mf][1] += e10 + e11;
                *(float2*)&attn_out[((size_t)bh * S + q0 + r0) * S + k0 + c0] =
                    make_float2(e00, e01);
                *(float2*)&attn_out[((size_t)bh * S + q0 + r0 + 8) * S + k0 + c0] =
                    make_float2(e10, e11);
                Ps[r0 * 68 + c0]       = f2tf32(e00);
                Ps[r0 * 68 + c0 + 1]   = f2tf32(e01);
                Ps[(r0 + 8) * 68 + c0]     = f2tf32(e10);
                Ps[(r0 + 8) * 68 + c0 + 1] = f2tf32(e11);
            }
        }

        cp_wait0();            // V(kt) arrived (thread-local)
        __syncthreads();       // publish V + Ps; Ks fully consumed

        // issue K(kt+1) into Ks — overlaps the P·V phase below
        if (kt + 1 < S / 64) {
            const int nk0 = k0 + 64;
#pragma unroll
            for (int i = 0; i < 4; i++) {
                int row = frow + i * 16;
                cp16(ks_u + (uint32_t)(row * 68 + fc4 * 4) * 4,
                     &g_kh[((size_t)bh * S + nk0 + row) * DK + fc4 * 4]);
            }
            cp_commit();
        }

        // ctx += P·V   (k = key, 8 steps; B = Vt[d][key]); cvt.rna on V frags
#pragma unroll
        for (int ks = 0; ks < 8; ks++) {
            const int kk = ks * 8;
            uint32_t a[2][4], b[4][2];
#pragma unroll
            for (int mf = 0; mf < 2; mf++) {
                const int row = wm + mf * 16 + g;
                a[mf][0] = Ps[row * 68 + kk + tq];
                a[mf][1] = Ps[(row + 8) * 68 + kk + tq];
                a[mf][2] = Ps[row * 68 + kk + tq + 4];
                a[mf][3] = Ps[(row + 8) * 68 + kk + tq + 4];
            }
#pragma unroll
            for (int nf = 0; nf < 4; nf++) {
                const int col = wn + nf * 8 + g;
                b[nf][0] = tf32b(Vt[col * 68 + kk + tq]);
                b[nf][1] = tf32b(Vt[col * 68 + kk + tq + 4]);
            }
#pragma unroll
            for (int mf = 0; mf < 2; mf++)
#pragma unroll
                for (int nf = 0; nf < 4; nf++)
                    mma_tf32(cacc[mf][nf], a[mf], b[nf]);
        }
        __syncthreads();       // Vt + Ps fully consumed

        // issue V(kt+1) into Vt — overlaps the next tile's QK phase
        if (kt + 1 < S / 64) {
            const int nk0 = k0 + 64;
#pragma unroll
            for (int i = 0; i < 4; i++) {
                int row = frow + i * 16;
                cp16(vt_u + (uint32_t)(row * 68 + fc4 * 4) * 4,
                     &g_vt[((size_t)bh * DK + row) * S + nk0 + fc4 * 4]);
            }
            cp_commit();
        }
    }

    // rowsum: reduce across tq lanes (same g), publish per warp-column
#pragma unroll
    for (int mf = 0; mf < 2; mf++)
#pragma unroll
        for (int hh = 0; hh < 2; hh++) {
            float v = rsum[mf][hh];
            v += __shfl_xor_sync(0xffffffffu, v, 1);
            v += __shfl_xor_sync(0xffffffffu, v, 2);
            rsum[mf][hh] = v;
        }
    if (tq == 0) {
#pragma unroll
        for (int mf = 0; mf < 2; mf++)
#pragma unroll
            for (int hh = 0; hh < 2; hh++)
                rs[(wid & 1) * 128 + wm + mf * 16 + hh * 8 + g] = rsum[mf][hh];
    }
    __syncthreads();
    if (tid < 128) {
        float iv = 1.0f / (rs[tid] + rs[128 + tid]);
        g_rinv[(size_t)bh * S + q0 + tid] = iv;
        sinv[tid] = iv;
    }
    __syncthreads();

    // scaled ctx -> g_ctx[(b*S+s)*D + h*64 + d]
    const int b_ = bh >> 4, h_ = bh & 15;
#pragma unroll
    for (int mf = 0; mf < 2; mf++) {
        const int r0 = wm + mf * 16 + g;
        const float iv0 = sinv[r0], iv1 = sinv[r0 + 8];
#pragma unroll
        for (int nf = 0; nf < 4; nf++) {
            const int c0 = wn + nf * 8 + tq * 2;
            *(float2*)&g_ctx[((size_t)b_ * S + q0 + r0) * D + h_ * DK + c0] =
                make_float2(cacc[mf][nf][0] * iv0, cacc[mf][nf][1] * iv0);
            *(float2*)&g_ctx[((size_t)b_ * S + q0 + r0 + 8) * D + h_ * DK + c0] =
                make_float2(cacc[mf][nf][2] * iv1, cacc[mf][nf][3] * iv1);
        }
    }
}

// ---------------------------------------------------------------------------
// K3: normalize attn in place:  attn[row][*] *= rinv[row]
// ---------------------------------------------------------------------------
__global__ __launch_bounds__(256) void attn_scale_kernel(float* __restrict__ attn)
{
    size_t idx4 = (size_t)blockIdx.x * blockDim.x + threadIdx.x;
    size_t row  = idx4 >> 9;
    float inv = g_rinv[row];
    float4* p = (float4*)attn + idx4;
    float4 v = *p;
    v.x *= inv; v.y *= inv; v.z *= inv; v.w *= inv;
    *p = v;
}

// ---------------------------------------------------------------------------
// K5: LayerNorm over last dim (1024). One block (256 thr) per row.
// ---------------------------------------------------------------------------
__global__ __launch_bounds__(256) void ln_kernel(
    const float* __restrict__ gamma, const float* __restrict__ beta,
    float* __restrict__ out)
{
    __shared__ float s1[8], s2[8];
    __shared__ float sm_mean, sm_rstd;
    const int row = blockIdx.x;
    const int t   = threadIdx.x;
    const float* x = g_x + (size_t)row * D;

    float4 v = *(const float4*)(x + t * 4);
    float sum = v.x + v.y + v.z + v.w;
    float sq  = v.x * v.x + v.y * v.y + v.z * v.z + v.w * v.w;
#pragma unroll
    for (int m = 16; m >= 1; m >>= 1) {
        sum += __shfl_xor_sync(0xffffffffu, sum, m);
        sq  += __shfl_xor_sync(0xffffffffu, sq, m);
    }
    const int warp = t >> 5, lane = t & 31;
    if (lane == 0) { s1[warp] = sum; s2[warp] = sq; }
    __syncthreads();
    if (t == 0) {
        float a = 0.f, c = 0.f;
#pragma unroll
        for (int w = 0; w < 8; w++) { a += s1[w]; c += s2[w]; }
        float mean = a * (1.0f / D);
        float var  = c * (1.0f / D) - mean * mean;
        sm_mean = mean;
        sm_rstd = rsqrtf(var + 1e-6f);
    }
    __syncthreads();
    const float mean = sm_mean, r = sm_rstd;
    float4 g4 = *(const float4*)(gamma + t * 4);
    float4 b4 = *(const float4*)(beta + t * 4);
    float4 o;
    o.x = (v.x - mean) * r * g4.x + b4.x;
    o.y = (v.y - mean) * r * g4.y + b4.y;
    o.z = (v.z - mean) * r * g4.z + b4.z;
    o.w = (v.w - mean) * r * g4.w + b4.w;
    *(float4*)(out + (size_t)row * D + t * 4) = o;
}

// ---------------------------------------------------------------------------
extern "C" void kernel_launch(void* const* d_in, const int* in_sizes, int n_in,
                              void* d_out, int out_size)
{
    const float* q     = (const float*)d_in[0];
    const float* k     = (const float*)d_in[1];
    const float* v     = (const float*)d_in[2];
    const float* Wq    = (const float*)d_in[3];
    const float* bq    = (const float*)d_in[4];
    const float* Wfc   = (const float*)d_in[5];
    const float* bfc   = (const float*)d_in[6];
    const float* gamma = (const float*)d_in[7];
    const float* beta  = (const float*)d_in[8];

    float* out_x    = (float*)d_out;
    float* out_attn = out_x + X_ELEMS;

    cudaFuncSetAttribute(gemm_mma_kernel,
                         cudaFuncAttributeMaxDynamicSharedMemorySize, GEMM_SMEM);
    cudaFuncSetAttribute(attn_mma_kernel,
                         cudaFuncAttributeMaxDynamicSharedMemorySize, ATTN_SMEM);

    float *wqt_p, *wfct_p, *qh_p, *kh_p, *vt_p, *ctx_p, *x_p;
    cudaGetSymbolAddress((void**)&wqt_p,  g_wqt);
    cudaGetSymbolAddress((void**)&wfct_p, g_wfct);
    cudaGetSymbolAddress((void**)&qh_p,   g_qh);
    cudaGetSymbolAddress((void**)&kh_p,   g_kh);
    cudaGetSymbolAddress((void**)&vt_p,   g_vt);
    cudaGetSymbolAddress((void**)&ctx_p,  g_ctx);
    cudaGetSymbolAddress((void**)&x_p,    g_x);

    transpose_kernel<<<dim3(32, 32, 2), dim3(32, 8)>>>(Wq, Wfc);
    gemm_mma_kernel<<<dim3(8, 64, 3), 256, GEMM_SMEM>>>(
        q, k, v, wqt_p, bq, nullptr, qh_p, kh_p, vt_p, 0);
    attn_mma_kernel<<<dim3(16, 64), 256, ATTN_SMEM>>>(out_attn);
    attn_scale_kernel<<<(unsigned)(ATTN_ELEMS / 4 / 256), 256>>>(out_attn);
    gemm_mma_kernel<<<dim3(8, 64, 1), 256, GEMM_SMEM>>>(
        ctx_p, ctx_p, ctx_p, wfct_p, bfc, q, x_p, x_p, x_p, 1);
    ln_kernel<<<B * S, 256>>>(gamma, beta, out_x);
}

// round 7
// speedup vs baseline: 1.4825x; 1.0010x over previous
#include <cuda_runtime.h>
#include <cstdint>

// ---------------------------------------------------------------------------
// MultiHeadAttention (B=4, S=2048, D=1024, H=16, DK=64).
// Round 7: R6 + (a) attn_scale overlapped with fc+ln via forked capture
// stream, (b) tf32 pre-rounding at producers (bit-identical numerics,
// fewer cvts on the hot paths), (c) streaming cache hints in attn_scale.
// Output layout: d_out = [ x (8,388,608 f32) | attn (268,435,456 f32) ]
// ---------------------------------------------------------------------------

namespace {
constexpr int B  = 4;
constexpr int S  = 2048;
constexpr int D  = 1024;
constexpr int H  = 16;
constexpr int DK = 64;
constexpr size_t QH_ELEMS   = (size_t)B * H * S * DK;        // 8,388,608
constexpr size_t X_ELEMS    = (size_t)B * S * D;             // 8,388,608
constexpr size_t ATTN_ELEMS = (size_t)B * H * S * (size_t)S; // 268,435,456

// dense-GEMM tiling: CTA 128x128, warp 64x32 (2x4 warps), K-chunk 32,
// two cp.async stages. Tile stride 36 words (=4 mod 32 -> conflict-free).
constexpr int KC  = 32;
constexpr int NCH = D / KC;                 // 32 chunks
constexpr int GST = 36;
constexpr int GTILE = 128 * GST;            // words per tile
constexpr int GEMM_SMEM = 4 * GTILE * 4;    // 73,728 B (As0,Bs0,As1,Bs1)

// attention smem layout (uint32 words)
constexpr int AQ_OFF = 0;                  // Qs[128][68] (tf32)
constexpr int AK_OFF = AQ_OFF + 128 * 68;  // Ks[64][68]  (tf32 bits via cp.async)
constexpr int AV_OFF = AK_OFF + 64 * 68;   // Vt[64][68]  (tf32 bits; d rows, key cols)
constexpr int AP_OFF = AV_OFF + 64 * 68;   // Ps[128][68] (tf32)
constexpr int ARS_OFF = AP_OFF + 128 * 68; // rs[2][128] floats
constexpr int AIV_OFF = ARS_OFF + 256;     // sinv[128] floats
constexpr int ATTN_SMEM = (AIV_OFF + 128) * 4;   // 105,984 B
}

// Scratch (allocation-free rule: __device__ globals)
__device__ float g_qh[QH_ELEMS];           // tf32-valued
__device__ float g_kh[QH_ELEMS];           // tf32-valued
__device__ float g_vt[QH_ELEMS];           // tf32-valued; V transposed [bh][d][s]
__device__ float g_ctx[X_ELEMS];           // tf32-valued
__device__ float g_x[X_ELEMS];             // fp32
__device__ float g_rinv[(size_t)B * H * S];
__device__ float g_wqt[(size_t)D * D];     // Wq^T  [N][K], tf32-valued
__device__ float g_wfct[(size_t)D * D];    // Wfc^T [N][K], tf32-valued

// ---------------------------------------------------------------------------
// helpers
// ---------------------------------------------------------------------------
__device__ __forceinline__ uint32_t smem_to_u32(const void* p) {
    uint32_t a;
    asm("{ .reg .u64 t; cvta.to.shared.u64 t, %1; cvt.u32.u64 %0, t; }"
        : "=r"(a) : "l"(p));
    return a;
}
__device__ __forceinline__ uint32_t f2tf32(float x) {
    uint32_t r;
    asm("cvt.rna.tf32.f32 %0, %1;" : "=r"(r) : "f"(x));
    return r;
}
__device__ __forceinline__ uint32_t tf32b(uint32_t rawbits) {
    return f2tf32(__uint_as_float(rawbits));
}
__device__ __forceinline__ void mma_tf32(float* d, const uint32_t* a, const uint32_t* b) {
    asm volatile(
        "mma.sync.aligned.m16n8k8.row.col.f32.tf32.tf32.f32 "
        "{%0,%1,%2,%3}, {%4,%5,%6,%7}, {%8,%9}, {%0,%1,%2,%3};"
        : "+f"(d[0]), "+f"(d[1]), "+f"(d[2]), "+f"(d[3])
        : "r"(a[0]), "r"(a[1]), "r"(a[2]), "r"(a[3]), "r"(b[0]), "r"(b[1]));
}
__device__ __forceinline__ void cp16(uint32_t dst, const void* src) {
    asm volatile("cp.async.cg.shared.global [%0], [%1], 16;" :: "r"(dst), "l"(src));
}
__device__ __forceinline__ void cp8(uint32_t dst, const void* src) {
    asm volatile("cp.async.ca.shared.global [%0], [%1], 8;" :: "r"(dst), "l"(src));
}
__device__ __forceinline__ void cp_commit() {
    asm volatile("cp.async.commit_group;" ::: "memory");
}
__device__ __forceinline__ void cp_wait0() {
    asm volatile("cp.async.wait_group 0;" ::: "memory");
}
__device__ __forceinline__ void cp_wait1() {
    asm volatile("cp.async.wait_group 1;" ::: "memory");
}
// exp via FMA pipe: magic-number range reduction + deg-5 poly (rel err ~2e-6).
__device__ __forceinline__ float fast_exp(float x) {
    const float L2E = 1.4426950408889634f;
    float t = fmaf(x, L2E, 12582912.0f);
    float n = t - 12582912.0f;
    float f = fmaf(x, L2E, -n);
    float p = 0.0013333558f;
    p = fmaf(p, f, 0.0096181291f);
    p = fmaf(p, f, 0.0555041087f);
    p = fmaf(p, f, 0.2402265069f);
    p = fmaf(p, f, 0.6931471806f);
    p = fmaf(p, f, 1.0f);
    return __int_as_float(__float_as_int(p) + (__float_as_int(t) << 23));
}

// ---------------------------------------------------------------------------
// K0: transpose Wq and Wfc once -> g_wqt / g_wfct (tf32-rounded at store)
// ---------------------------------------------------------------------------
__global__ __launch_bounds__(256) void transpose_kernel(
    const float* __restrict__ Wq, const float* __restrict__ Wfc)
{
    __shared__ float tile[32][33];
    const float* src = blockIdx.z ? Wfc : Wq;
    float*       dst = blockIdx.z ? g_wfct : g_wqt;
    int x = blockIdx.x * 32 + threadIdx.x;
    int y = blockIdx.y * 32 + threadIdx.y;
#pragma unroll
    for (int i = 0; i < 32; i += 8)
        tile[threadIdx.y + i][threadIdx.x] = src[(size_t)(y + i) * D + x];
    __syncthreads();
    int tx = blockIdx.y * 32 + threadIdx.x;
    int ty = blockIdx.x * 32 + threadIdx.y;
#pragma unroll
    for (int i = 0; i < 32; i += 8)
        dst[(size_t)(ty + i) * D + tx] =
            __uint_as_float(f2tf32(tile[threadIdx.x][threadIdx.y + i]));
}

// ---------------------------------------------------------------------------
// K1/K4: tf32 mma.sync GEMM, 2-stage cp.async pipeline.
// Y[m,n] = A[m,:] . Bt[n,:]  (+bias[, +resid])
// mode 0: proj layout; z=0,1 -> qh/kh rows; z=2 -> V TRANSPOSED to g_vt.
//         A raw fp32 (cvt at fragment load); outputs tf32-rounded.
// mode 1: fc. A (g_ctx) and B pre-rounded -> no cvts; output fp32 + resid.
// ---------------------------------------------------------------------------
__global__ __launch_bounds__(256) void gemm_mma_kernel(
    const float* __restrict__ A0, const float* __restrict__ A1,
    const float* __restrict__ A2, const float* __restrict__ Bt,
    const float* __restrict__ bias, const float* __restrict__ resid,
    float* __restrict__ O0, float* __restrict__ O1, float* __restrict__ O2,
    int mode)
{
    extern __shared__ uint32_t smu[];
    const uint32_t smem_u = smem_to_u32(smu);

    const int tid  = threadIdx.x;
    const int wid  = tid >> 5, lane = tid & 31;
    const int g    = lane >> 2, tq = lane & 3;
    const int wm   = (wid >> 2) * 64;
    const int wn   = (wid & 3) * 32;
    const int n0   = blockIdx.x * 128;
    const int m0   = blockIdx.y * 128;

    const float* Ap;
    float* Op;
    if (blockIdx.z == 0)      { Ap = A0; Op = O0; }
    else if (blockIdx.z == 1) { Ap = A1; Op = O1; }
    else                      { Ap = A2; Op = O2; }

    float acc[4][4][4];
#pragma unroll
    for (int i = 0; i < 4; i++)
#pragma unroll
        for (int j = 0; j < 4; j++)
#pragma unroll
            for (int r = 0; r < 4; r++) acc[i][j][r] = 0.f;

    // prologue: issue chunks 0 (stage 0) and 1 (stage 1)
#pragma unroll
    for (int c0 = 0; c0 < 2; c0++) {
        const int kt = c0 * KC;
        const uint32_t sbase = smem_u + (uint32_t)(c0 * 2 * GTILE) * 4;
#pragma unroll
        for (int j = 0; j < 8; j++) {
            int idx = tid + j * 256;          // 2048 8B-chunks per tile
            int row = idx >> 4, ch = idx & 15;
            uint32_t off = (uint32_t)(row * GST + ch * 2) * 4;
            cp8(sbase + off,             Ap + (size_t)(m0 + row) * D + kt + ch * 2);
            cp8(sbase + off + GTILE * 4, Bt + (size_t)(n0 + row) * D + kt + ch * 2);
        }
        cp_commit();
    }

    for (int c = 0; c < NCH; c++) {
        const int st = c & 1;
        if (c + 1 < NCH) cp_wait1(); else cp_wait0();
        __syncthreads();

        const uint32_t* As = smu + st * 2 * GTILE;
        const uint32_t* Bs = As + GTILE;

#pragma unroll
        for (int ks = 0; ks < KC / 8; ks++) {
            const int kk = ks * 8;
            uint32_t a[4][4], b[4][2];
            if (mode == 0) {
#pragma unroll
                for (int mf = 0; mf < 4; mf++) {
                    const int row = wm + mf * 16 + g;
                    a[mf][0] = tf32b(As[row * GST + kk + tq]);
                    a[mf][1] = tf32b(As[(row + 8) * GST + kk + tq]);
                    a[mf][2] = tf32b(As[row * GST + kk + tq + 4]);
                    a[mf][3] = tf32b(As[(row + 8) * GST + kk + tq + 4]);
                }
            } else {
#pragma unroll
                for (int mf = 0; mf < 4; mf++) {
                    const int row = wm + mf * 16 + g;
                    a[mf][0] = As[row * GST + kk + tq];
                    a[mf][1] = As[(row + 8) * GST + kk + tq];
                    a[mf][2] = As[row * GST + kk + tq + 4];
                    a[mf][3] = As[(row + 8) * GST + kk + tq + 4];
                }
            }
#pragma unroll
            for (int nf = 0; nf < 4; nf++) {
                const int col = wn + nf * 8 + g;
                b[nf][0] = Bs[col * GST + kk + tq];
                b[nf][1] = Bs[col * GST + kk + tq + 4];
            }
#pragma unroll
            for (int mf = 0; mf < 4; mf++)
#pragma unroll
                for (int nf = 0; nf < 4; nf++)
                    mma_tf32(acc[mf][nf], a[mf], b[nf]);
        }
        __syncthreads();

        // refill this stage with chunk c+2 (overlaps chunk c+1's compute)
        if (c + 2 < NCH) {
            const int kt = (c + 2) * KC;
            const uint32_t sbase = smem_u + (uint32_t)(st * 2 * GTILE) * 4;
#pragma unroll
            for (int j = 0; j < 8; j++) {
                int idx = tid + j * 256;
                int row = idx >> 4, ch = idx & 15;
                uint32_t off = (uint32_t)(row * GST + ch * 2) * 4;
                cp8(sbase + off,             Ap + (size_t)(m0 + row) * D + kt + ch * 2);
                cp8(sbase + off + GTILE * 4, Bt + (size_t)(n0 + row) * D + kt + ch * 2);
            }
            cp_commit();
        }
    }

#pragma unroll
    for (int mf = 0; mf < 4; mf++) {
#pragma unroll
        for (int nf = 0; nf < 4; nf++) {
            const int m = m0 + wm + mf * 16 + g;
            const int n = n0 + wn + nf * 8 + tq * 2;
            float bx = bias[n], by = bias[n + 1];
#pragma unroll
            for (int half = 0; half < 2; half++) {
                const int mm = m + half * 8;
                float vx = acc[mf][nf][half * 2 + 0] + bx;
                float vy = acc[mf][nf][half * 2 + 1] + by;
                if (mode == 0) {
                    // outputs feed MMA only -> tf32-round at producer
                    vx = __uint_as_float(f2tf32(vx));
                    vy = __uint_as_float(f2tf32(vy));
                    const int h = n >> 6, dk = n & 63;
                    const int bb_ = mm >> 11, s = mm & 2047;
                    if (blockIdx.z == 2) {
                        float* vtb = &g_vt[(((size_t)bb_ * H + h) * DK + dk) * S + s];
                        vtb[0] = vx;
                        vtb[S] = vy;
                    } else {
                        float2* p = (float2*)&Op[(((size_t)bb_ * H + h) * S + s) * DK + dk];
                        *p = make_float2(vx, vy);
                    }
                } else {
                    const float* rr = resid + (size_t)mm * D + n;
                    float2 r2 = *(const float2*)rr;
                    float2* p = (float2*)&Op[(size_t)mm * D + n];
                    *p = make_float2(vx + r2.x, vy + r2.y);
                }
            }
        }
    }
}

// ---------------------------------------------------------------------------
// K2: attention via tf32 mma.sync, cp.async K/V slid into dead phases.
// grid (16 q-tiles, 64 bh), block 256. Warp grid 4x2.
// K/V/Q arrive pre-rounded to tf32 -> fragment loads are plain LDS.
// ---------------------------------------------------------------------------
__global__ __launch_bounds__(256, 2) void attn_mma_kernel(float* __restrict__ attn_out)
{
    extern __shared__ uint32_t smu[];
    uint32_t* Qs = smu + AQ_OFF;
    uint32_t* Ks = smu + AK_OFF;
    uint32_t* Vt = smu + AV_OFF;
    uint32_t* Ps = smu + AP_OFF;
    float* rs    = (float*)(smu + ARS_OFF);
    float* sinv  = (float*)(smu + AIV_OFF);
    const uint32_t smem_u = smem_to_u32(smu);
    const uint32_t ks_u = smem_u + AK_OFF * 4;
    const uint32_t vt_u = smem_u + AV_OFF * 4;

    const int bh = blockIdx.y;
    const int q0 = blockIdx.x * 128;
    const int tid = threadIdx.x;
    const int wid = tid >> 5, lane = tid & 31;
    const int g = lane >> 2, tq = lane & 3;
    const int wm = (wid >> 1) * 32;
    const int wn = (wid & 1) * 32;
    const float scale = 0.125f;

    const int frow = tid >> 4, fc4 = tid & 15;     // K/V fill: rows frow + i*16

    // Q tile: g_qh is tf32-valued; *0.125 is exact -> store bits directly
#pragma unroll
    for (int i = 0; i < 8; i++) {
        int f4 = tid + i * 256;
        int row = f4 >> 4, c4 = f4 & 15;
        float4 qv = *(const float4*)&g_qh[((size_t)bh * S + q0 + row) * DK + c4 * 4];
        uint32_t* qd = &Qs[row * 68 + c4 * 4];
        qd[0] = __float_as_uint(qv.x * scale);
        qd[1] = __float_as_uint(qv.y * scale);
        qd[2] = __float_as_uint(qv.z * scale);
        qd[3] = __float_as_uint(qv.w * scale);
    }

    // prologue: issue K(0) then V(0) as separate groups
#pragma unroll
    for (int i = 0; i < 4; i++) {
        int row = frow + i * 16;
        cp16(ks_u + (uint32_t)(row * 68 + fc4 * 4) * 4,
             &g_kh[((size_t)bh * S + row) * DK + fc4 * 4]);
    }
    cp_commit();
#pragma unroll
    for (int i = 0; i < 4; i++) {
        int row = frow + i * 16;
        cp16(vt_u + (uint32_t)(row * 68 + fc4 * 4) * 4,
             &g_vt[((size_t)bh * DK + row) * S + fc4 * 4]);
    }
    cp_commit();

    float cacc[2][4][4];
    float rsum[2][2] = {{0.f, 0.f}, {0.f, 0.f}};
#pragma unroll
    for (int mf = 0; mf < 2; mf++)
#pragma unroll
        for (int nf = 0; nf < 4; nf++)
#pragma unroll
            for (int r = 0; r < 4; r++) cacc[mf][nf][r] = 0.f;

    for (int kt = 0; kt < S / 64; kt++) {
        const int k0 = kt * 64;

        cp_wait1();            // K(kt) arrived (V(kt) may still be in flight)
        __syncthreads();

        // S = Q·K^T  (k = d, 8 steps); operands already tf32
        float sacc[2][4][4];
#pragma unroll
        for (int mf = 0; mf < 2; mf++)
#pragma unroll
            for (int nf = 0; nf < 4; nf++)
#pragma unroll
                for (int r = 0; r < 4; r++) sacc[mf][nf][r] = 0.f;
#pragma unroll
        for (int ks = 0; ks < 8; ks++) {
            const int kk = ks * 8;
            uint32_t a[2][4], b[4][2];
#pragma unroll
            for (int mf = 0; mf < 2; mf++) {
                const int row = wm + mf * 16 + g;
                a[mf][0] = Qs[row * 68 + kk + tq];
                a[mf][1] = Qs[(row + 8) * 68 + kk + tq];
                a[mf][2] = Qs[row * 68 + kk + tq + 4];
                a[mf][3] = Qs[(row + 8) * 68 + kk + tq + 4];
            }
#pragma unroll
            for (int nf = 0; nf < 4; nf++) {
                const int col = wn + nf * 8 + g;
                b[nf][0] = Ks[col * 68 + kk + tq];
                b[nf][1] = Ks[col * 68 + kk + tq + 4];
            }
#pragma unroll
            for (int mf = 0; mf < 2; mf++)
#pragma unroll
                for (int nf = 0; nf < 4; nf++)
                    mma_tf32(sacc[mf][nf], a[mf], b[nf]);
        }

        // exp, rowsum, E -> gmem (unnormalized), P -> smem (tf32)
#pragma unroll
        for (int mf = 0; mf < 2; mf++) {
            const int r0 = wm + mf * 16 + g;
#pragma unroll
            for (int nf = 0; nf < 4; nf++) {
                const int c0 = wn + nf * 8 + tq * 2;
                float e00 = fast_exp(sacc[mf][nf][0]);
                float e01 = fast_exp(sacc[mf][nf][1]);
                float e10 = fast_exp(sacc[mf][nf][2]);
                float e11 = fast_exp(sacc[mf][nf][3]);
                rsum[mf][0] += e00 + e01;
                rsum[mf][1] += e10 + e11;
                *(float2*)&attn_out[((size_t)bh * S + q0 + r0) * S + k0 + c0] =
                    make_float2(e00, e01);
                *(float2*)&attn_out[((size_t)bh * S + q0 + r0 + 8) * S + k0 + c0] =
                    make_float2(e10, e11);
                Ps[r0 * 68 + c0]       = f2tf32(e00);
                Ps[r0 * 68 + c0 + 1]   = f2tf32(e01);
                Ps[(r0 + 8) * 68 + c0]     = f2tf32(e10);
                Ps[(r0 + 8) * 68 + c0 + 1] = f2tf32(e11);
            }
        }

        cp_wait0();            // V(kt) arrived
        __syncthreads();       // publish V + Ps; Ks fully consumed

        // issue K(kt+1) into Ks — overlaps the P·V phase below
        if (kt + 1 < S / 64) {
            const int nk0 = k0 + 64;
#pragma unroll
            for (int i = 0; i < 4; i++) {
                int row = frow + i * 16;
                cp16(ks_u + (uint32_t)(row * 68 + fc4 * 4) * 4,
                     &g_kh[((size_t)bh * S + nk0 + row) * DK + fc4 * 4]);
            }
            cp_commit();
        }

        // ctx += P·V   (k = key, 8 steps; B = Vt[d][key], already tf32)
#pragma unroll
        for (int ks = 0; ks < 8; ks++) {
            const int kk = ks * 8;
            uint32_t a[2][4], b[4][2];
#pragma unroll
            for (int mf = 0; mf < 2; mf++) {
                const int row = wm + mf * 16 + g;
                a[mf][0] = Ps[row * 68 + kk + tq];
                a[mf][1] = Ps[(row + 8) * 68 + kk + tq];
                a[mf][2] = Ps[row * 68 + kk + tq + 4];
                a[mf][3] = Ps[(row + 8) * 68 + kk + tq + 4];
            }
#pragma unroll
            for (int nf = 0; nf < 4; nf++) {
                const int col = wn + nf * 8 + g;
                b[nf][0] = Vt[col * 68 + kk + tq];
                b[nf][1] = Vt[col * 68 + kk + tq + 4];
            }
#pragma unroll
            for (int mf = 0; mf < 2; mf++)
#pragma unroll
                for (int nf = 0; nf < 4; nf++)
                    mma_tf32(cacc[mf][nf], a[mf], b[nf]);
        }
        __syncthreads();       // Vt + Ps fully consumed

        // issue V(kt+1) into Vt — overlaps the next tile's QK phase
        if (kt + 1 < S / 64) {
            const int nk0 = k0 + 64;
#pragma unroll
            for (int i = 0; i < 4; i++) {
                int row = frow + i * 16;
                cp16(vt_u + (uint32_t)(row * 68 + fc4 * 4) * 4,
                     &g_vt[((size_t)bh * DK + row) * S + nk0 + fc4 * 4]);
            }
            cp_commit();
        }
    }

    // rowsum: reduce across tq lanes (same g), publish per warp-column
#pragma unroll
    for (int mf = 0; mf < 2; mf++)
#pragma unroll
        for (int hh = 0; hh < 2; hh++) {
            float v = rsum[mf][hh];
            v += __shfl_xor_sync(0xffffffffu, v, 1);
            v += __shfl_xor_sync(0xffffffffu, v, 2);
            rsum[mf][hh] = v;
        }
    if (tq == 0) {
#pragma unroll
        for (int mf = 0; mf < 2; mf++)
#pragma unroll
            for (int hh = 0; hh < 2; hh++)
                rs[(wid & 1) * 128 + wm + mf * 16 + hh * 8 + g] = rsum[mf][hh];
    }
    __syncthreads();
    if (tid < 128) {
        float iv = 1.0f / (rs[tid] + rs[128 + tid]);
        g_rinv[(size_t)bh * S + q0 + tid] = iv;
        sinv[tid] = iv;
    }
    __syncthreads();

    // scaled ctx -> g_ctx (tf32-rounded: consumed only by fc's MMA)
    const int b_ = bh >> 4, h_ = bh & 15;
#pragma unroll
    for (int mf = 0; mf < 2; mf++) {
        const int r0 = wm + mf * 16 + g;
        const float iv0 = sinv[r0], iv1 = sinv[r0 + 8];
#pragma unroll
        for (int nf = 0; nf < 4; nf++) {
            const int c0 = wn + nf * 8 + tq * 2;
            *(float2*)&g_ctx[((size_t)b_ * S + q0 + r0) * D + h_ * DK + c0] =
                make_float2(__uint_as_float(f2tf32(cacc[mf][nf][0] * iv0)),
                            __uint_as_float(f2tf32(cacc[mf][nf][1] * iv0)));
            *(float2*)&g_ctx[((size_t)b_ * S + q0 + r0 + 8) * D + h_ * DK + c0] =
                make_float2(__uint_as_float(f2tf32(cacc[mf][nf][2] * iv1)),
                            __uint_as_float(f2tf32(cacc[mf][nf][3] * iv1)));
        }
    }
}

// ---------------------------------------------------------------------------
// K3: normalize attn in place:  attn[row][*] *= rinv[row]  (streaming hints)
// ---------------------------------------------------------------------------
__global__ __launch_bounds__(256) void attn_scale_kernel(float* __restrict__ attn)
{
    size_t idx4 = (size_t)blockIdx.x * blockDim.x + threadIdx.x;
    size_t row  = idx4 >> 9;
    float inv = g_rinv[row];
    float4* p = (float4*)attn + idx4;
    float4 v = __ldcs(p);
    v.x *= inv; v.y *= inv; v.z *= inv; v.w *= inv;
    __stcs(p, v);
}

// ---------------------------------------------------------------------------
// K5: LayerNorm over last dim (1024). One block (256 thr) per row.
// ---------------------------------------------------------------------------
__global__ __launch_bounds__(256) void ln_kernel(
    const float* __restrict__ gamma, const float* __restrict__ beta,
    float* __restrict__ out)
{
    __shared__ float s1[8], s2[8];
    __shared__ float sm_mean, sm_rstd;
    const int row = blockIdx.x;
    const int t   = threadIdx.x;
    const float* x = g_x + (size_t)row * D;

    float4 v = *(const float4*)(x + t * 4);
    float sum = v.x + v.y + v.z + v.w;
    float sq  = v.x * v.x + v.y * v.y + v.z * v.z + v.w * v.w;
#pragma unroll
    for (int m = 16; m >= 1; m >>= 1) {
        sum += __shfl_xor_sync(0xffffffffu, sum, m);
        sq  += __shfl_xor_sync(0xffffffffu, sq, m);
    }
    const int warp = t >> 5, lane = t & 31;
    if (lane == 0) { s1[warp] = sum; s2[warp] = sq; }
    __syncthreads();
    if (t == 0) {
        float a = 0.f, c = 0.f;
#pragma unroll
        for (int w = 0; w < 8; w++) { a += s1[w]; c += s2[w]; }
        float mean = a * (1.0f / D);
        float var  = c * (1.0f / D) - mean * mean;
        sm_mean = mean;
        sm_rstd = rsqrtf(var + 1e-6f);
    }
    __syncthreads();
    const float mean = sm_mean, r = sm_rstd;
    float4 g4 = *(const float4*)(gamma + t * 4);
    float4 b4 = *(const float4*)(beta + t * 4);
    float4 o;
    o.x = (v.x - mean) * r * g4.x + b4.x;
    o.y = (v.y - mean) * r * g4.y + b4.y;
    o.z = (v.z - mean) * r * g4.z + b4.z;
    o.w = (v.w - mean) * r * g4.w + b4.w;
    *(float4*)(out + (size_t)row * D + t * 4) = o;
}

// ---------------------------------------------------------------------------
extern "C" void kernel_launch(void* const* d_in, const int* in_sizes, int n_in,
                              void* d_out, int out_size)
{
    const float* q     = (const float*)d_in[0];
    const float* k     = (const float*)d_in[1];
    const float* v     = (const float*)d_in[2];
    const float* Wq    = (const float*)d_in[3];
    const float* bq    = (const float*)d_in[4];
    const float* Wfc   = (const float*)d_in[5];
    const float* bfc   = (const float*)d_in[6];
    const float* gamma = (const float*)d_in[7];
    const float* beta  = (const float*)d_in[8];

    float* out_x    = (float*)d_out;
    float* out_attn = out_x + X_ELEMS;

    cudaFuncSetAttribute(gemm_mma_kernel,
                         cudaFuncAttributeMaxDynamicSharedMemorySize, GEMM_SMEM);
    cudaFuncSetAttribute(attn_mma_kernel,
                         cudaFuncAttributeMaxDynamicSharedMemorySize, ATTN_SMEM);

    float *wqt_p, *wfct_p, *qh_p, *kh_p, *vt_p, *ctx_p, *x_p;
    cudaGetSymbolAddress((void**)&wqt_p,  g_wqt);
    cudaGetSymbolAddress((void**)&wfct_p, g_wfct);
    cudaGetSymbolAddress((void**)&qh_p,   g_qh);
    cudaGetSymbolAddress((void**)&kh_p,   g_kh);
    cudaGetSymbolAddress((void**)&vt_p,   g_vt);
    cudaGetSymbolAddress((void**)&ctx_p,  g_ctx);
    cudaGetSymbolAddress((void**)&x_p,    g_x);

    // fork/join resources (created + destroyed per call: mem delta stays 0)
    cudaStream_t s2;
    cudaEvent_t evFork, evJoin;
    cudaStreamCreateWithFlags(&s2, cudaStreamNonBlocking);
    cudaEventCreateWithFlags(&evFork, cudaEventDisableTiming);
    cudaEventCreateWithFlags(&evJoin, cudaEventDisableTiming);

    transpose_kernel<<<dim3(32, 32, 2), dim3(32, 8)>>>(Wq, Wfc);
    gemm_mma_kernel<<<dim3(8, 64, 3), 256, GEMM_SMEM>>>(
        q, k, v, wqt_p, bq, nullptr, qh_p, kh_p, vt_p, 0);
    attn_mma_kernel<<<dim3(16, 64), 256, ATTN_SMEM>>>(out_attn);

    // fork: attn_scale (stream s2)  ||  fc -> ln (main stream)
    cudaEventRecord(evFork, 0);
    cudaStreamWaitEvent(s2, evFork, 0);
    attn_scale_kernel<<<(unsigned)(ATTN_ELEMS / 4 / 256), 256, 0, s2>>>(out_attn);

    gemm_mma_kernel<<<dim3(8, 64, 1), 256, GEMM_SMEM>>>(
        ctx_p, ctx_p, ctx_p, wfct_p, bfc, q, x_p, x_p, x_p, 1);
    ln_kernel<<<B * S, 256>>>(gamma, beta, out_x);

    // join
    cudaEventRecord(evJoin, s2);
    cudaStreamWaitEvent(0, evJoin, 0);

    cudaEventDestroy(evFork);
    cudaEventDestroy(evJoin);
    cudaStreamDestroy(s2);
}